// round 7
// baseline (speedup 1.0000x reference)
#include <cuda_runtime.h>
#include <cstdint>

// Aggregator: masked mean of sampled neighbor features.
//  d_in[0] features:      [N, 128] float32
//  d_in[1] neighbor_idx:  [N, 16]  int32
//  d_in[2] neighbor_mask: [N, 16]  int32 (0/1)
//  d_out   out:           [N, 128] float32
//
// TWO nodes per warp. Lane l loads idx/mask element l of the pair's 32
// combined slots (coalesced 128B loads), __ballot builds a 32-bit activity
// mask (warp-uniform), __shfl broadcasts indices at use. Fully unrolled
// 32-iter loop predicated on the uniform mask bit -> ~24 outstanding
// LDG.128 per warp. Accumulation uses packed f32x2 adds.

#define S 16
#define D 128

__device__ __forceinline__ unsigned long long addx2(unsigned long long a, unsigned long long b) {
    unsigned long long r;
    asm("add.rn.f32x2 %0, %1, %2;" : "=l"(r) : "l"(a), "l"(b));
    return r;
}

__global__ __launch_bounds__(256) void agg_kernel(
    const float* __restrict__ feat,
    const int* __restrict__ nidx,
    const int* __restrict__ mask,
    float* __restrict__ out,
    int n)
{
    int warp = (int)((blockIdx.x * (unsigned)blockDim.x + threadIdx.x) >> 5);
    int lane = threadIdx.x & 31;
    int node0 = 2 * warp;
    if (node0 >= n) return;
    int my_node = node0 + (lane >> 4);          // node owning this lane's idx/mask slot

    // ---- coalesced per-lane idx + mask loads (128B each across warp) ----
    size_t base = (size_t)warp * 32;
    int my_idx = 0, my_msk = 0;
    if (my_node < n) {
        my_idx = __ldg(nidx + base + lane);
        my_msk = __ldg(mask + base + lane);
    }
    unsigned ball = __ballot_sync(0xFFFFFFFFu, my_msk != 0);   // warp-uniform
    int cnt0 = __popc(ball & 0xFFFFu);
    int cnt1 = __popc(ball >> 16);

    // ---- packed f32x2 accumulators: (x,y) and (z,w) per node ----
    unsigned long long a0lo = 0ull, a0hi = 0ull;   // bitwise 0 == (0.0f, 0.0f)
    unsigned long long a1lo = 0ull, a1hi = 0ull;

#pragma unroll
    for (int j = 0; j < 32; j++) {
        // ball is warp-uniform: every lane takes the same branch -> the
        // __shfl_sync inside stays convergent.
        if ((ball >> j) & 1u) {
            int id = __shfl_sync(0xFFFFFFFFu, my_idx, j);
            const float4* row = reinterpret_cast<const float4*>(feat + (size_t)id * D);
            float4 v = __ldg(row + lane);                       // 512B coalesced per warp
            unsigned long long vlo, vhi;
            asm("mov.b64 %0, {%1, %2};" : "=l"(vlo) : "f"(v.x), "f"(v.y));
            asm("mov.b64 %0, {%1, %2};" : "=l"(vhi) : "f"(v.z), "f"(v.w));
            if (j < 16) { a0lo = addx2(a0lo, vlo); a0hi = addx2(a0hi, vhi); }
            else        { a1lo = addx2(a1lo, vlo); a1hi = addx2(a1hi, vhi); }
        }
    }

    // ---- scale by 1/count and store ----
    float inv0 = 1.0f / (float)(cnt0 > 0 ? cnt0 : 1);
    float inv1 = 1.0f / (float)(cnt1 > 0 ? cnt1 : 1);

    {
        float x, y, z, w;
        asm("mov.b64 {%0, %1}, %2;" : "=f"(x), "=f"(y) : "l"(a0lo));
        asm("mov.b64 {%0, %1}, %2;" : "=f"(z), "=f"(w) : "l"(a0hi));
        float4 r = make_float4(x * inv0, y * inv0, z * inv0, w * inv0);
        reinterpret_cast<float4*>(out)[(size_t)node0 * (D / 4) + lane] = r;
    }
    if (node0 + 1 < n) {
        float x, y, z, w;
        asm("mov.b64 {%0, %1}, %2;" : "=f"(x), "=f"(y) : "l"(a1lo));
        asm("mov.b64 {%0, %1}, %2;" : "=f"(z), "=f"(w) : "l"(a1hi));
        float4 r = make_float4(x * inv1, y * inv1, z * inv1, w * inv1);
        reinterpret_cast<float4*>(out)[(size_t)(node0 + 1) * (D / 4) + lane] = r;
    }
}

extern "C" void kernel_launch(void* const* d_in, const int* in_sizes, int n_in,
                              void* d_out, int out_size)
{
    const float* feat = (const float*)d_in[0];
    const int*   nidx = (const int*)d_in[1];
    const int*   mask = (const int*)d_in[2];
    float*       out  = (float*)d_out;

    int n = in_sizes[1] / S;                    // 100000 nodes
    int pairs = (n + 1) / 2;                    // warps needed (2 nodes/warp)
    int warps_per_block = 256 / 32;             // 8
    int blocks = (pairs + warps_per_block - 1) / warps_per_block;
    agg_kernel<<<blocks, 256>>>(feat, nidx, mask, out, n);
}

// round 8
// speedup vs baseline: 1.0800x; 1.0800x over previous
#include <cuda_runtime.h>
#include <cstdint>

// Aggregator: masked mean of sampled neighbor features.
//  d_in[0] features:      [N, 128] float32
//  d_in[1] neighbor_idx:  [N, 16]  int32
//  d_in[2] neighbor_mask: [N, 16]  int32 (0/1)
//  d_out   out:           [N, 128] float32
//
// One warp per node; lane l owns float4 columns [4l, 4l+4).
// All 16 gathers get dedicated dest buffers (v[16]) so the predicated
// LDG.128s issue back-to-back with no WAR chains -> MLP ~= 16/warp.
// Accumulation afterward with packed f32x2 adds (2 independent chains).
// High register use (~90) deliberately trades occupancy for MLP: the
// bottleneck is L1tex wavefront throughput, which needs deep load queues.

#define S 16
#define D 128

__device__ __forceinline__ unsigned long long addx2(unsigned long long a, unsigned long long b) {
    unsigned long long r;
    asm("add.rn.f32x2 %0, %1, %2;" : "=l"(r) : "l"(a), "l"(b));
    return r;
}

__global__ __launch_bounds__(256) void agg_kernel(
    const float* __restrict__ feat,
    const int* __restrict__ nidx,
    const int* __restrict__ mask,
    float* __restrict__ out,
    int n)
{
    int warp = (int)((blockIdx.x * (unsigned)blockDim.x + threadIdx.x) >> 5);
    int lane = threadIdx.x & 31;
    if (warp >= n) return;

    // ---- 16 int32 mask values as 4x int4 (uniform across warp) ----
    const int4* mp = reinterpret_cast<const int4*>(mask + (size_t)warp * S);
    unsigned nz = 0;
#pragma unroll
    for (int q = 0; q < 4; q++) {
        int4 m = __ldg(mp + q);
        nz |= (unsigned)(m.x != 0) << (4 * q + 0);
        nz |= (unsigned)(m.y != 0) << (4 * q + 1);
        nz |= (unsigned)(m.z != 0) << (4 * q + 2);
        nz |= (unsigned)(m.w != 0) << (4 * q + 3);
    }
    int cnt = __popc(nz);

    // ---- 16 int32 indices as 4x int4 (uniform across warp) ----
    const int4* ip = reinterpret_cast<const int4*>(nidx + (size_t)warp * S);
    int idx[S];
#pragma unroll
    for (int q = 0; q < 4; q++) {
        int4 v = __ldg(ip + q);
        idx[4 * q + 0] = v.x; idx[4 * q + 1] = v.y;
        idx[4 * q + 2] = v.z; idx[4 * q + 3] = v.w;
    }

    // ---- issue ALL 16 predicated gathers into dedicated buffers ----
    const float4 zero = make_float4(0.f, 0.f, 0.f, 0.f);
    float4 v[S];
#pragma unroll
    for (int j = 0; j < S; j++) {
        const float4* row = reinterpret_cast<const float4*>(feat + (size_t)idx[j] * D) + lane;
        v[j] = ((nz >> j) & 1u) ? __ldg(row) : zero;   // predicated LDG.128, no WAR chain
    }

    // ---- accumulate with packed f32x2, two independent chains ----
    unsigned long long aLo0 = 0ull, aHi0 = 0ull;   // bitwise 0 == (0.f, 0.f)
    unsigned long long aLo1 = 0ull, aHi1 = 0ull;
#pragma unroll
    for (int j = 0; j < S; j += 2) {
        unsigned long long lo, hi;
        asm("mov.b64 %0, {%1, %2};" : "=l"(lo) : "f"(v[j].x), "f"(v[j].y));
        asm("mov.b64 %0, {%1, %2};" : "=l"(hi) : "f"(v[j].z), "f"(v[j].w));
        aLo0 = addx2(aLo0, lo); aHi0 = addx2(aHi0, hi);
        asm("mov.b64 %0, {%1, %2};" : "=l"(lo) : "f"(v[j + 1].x), "f"(v[j + 1].y));
        asm("mov.b64 %0, {%1, %2};" : "=l"(hi) : "f"(v[j + 1].z), "f"(v[j + 1].w));
        aLo1 = addx2(aLo1, lo); aHi1 = addx2(aHi1, hi);
    }
    unsigned long long aLo = addx2(aLo0, aLo1);
    unsigned long long aHi = addx2(aHi0, aHi1);

    // ---- scale by 1/count and store ----
    float inv = 1.0f / (float)(cnt > 0 ? cnt : 1);
    float x, y, z, w;
    asm("mov.b64 {%0, %1}, %2;" : "=f"(x), "=f"(y) : "l"(aLo));
    asm("mov.b64 {%0, %1}, %2;" : "=f"(z), "=f"(w) : "l"(aHi));
    float4 r = make_float4(x * inv, y * inv, z * inv, w * inv);
    reinterpret_cast<float4*>(out)[(size_t)warp * (D / 4) + lane] = r;
}

extern "C" void kernel_launch(void* const* d_in, const int* in_sizes, int n_in,
                              void* d_out, int out_size)
{
    const float* feat = (const float*)d_in[0];
    const int*   nidx = (const int*)d_in[1];
    const int*   mask = (const int*)d_in[2];
    float*       out  = (float*)d_out;

    int n = in_sizes[1] / S;              // 100000 nodes
    int warps_per_block = 256 / 32;       // 8 warps/block
    int blocks = (n + warps_per_block - 1) / warps_per_block;
    agg_kernel<<<blocks, 256>>>(feat, nidx, mask, out, n);
}